// round 10
// baseline (speedup 1.0000x reference)
#include <cuda_runtime.h>

// Occupancy connectivity loss over a 385^3 fp32 grid, C order:
//   f = x*385^2 + y*385 + z
// Block = 8 warps = 8 consecutive y-rows of a 128-wide z segment (+1 halo
// column), marching over an x chunk. Per plane each warp loads its row ONCE
// (4 coalesced LDG.32 + lane31 halo) into prefetch regs consumed only in the
// NEXT iteration (full-iteration latency slack):
//   x-diff: |v - prev plane's smem row| (4-buffer rotation keeps it live)
//   z-diff: own smem row at [idx+1] (conflict-free scalar LDS)
//   y-diff: neighbor warp's smem row
// Rows loaded 8, owned 7. 8 blocks/SM.

#define ROW    385u
#define PLANE  148225u
#define WPB    8u
#define OWN    7u
#define NYG    55u
#define XC     7u
#define NZSEG  3u
#define NBLOCKS (NZSEG * NYG * XC)   // 1155

__device__ double   g_part[NBLOCKS];
__device__ unsigned g_count = 0;

__global__ void __launch_bounds__(256, 8)
occ_main(const float* __restrict__ occ, float* __restrict__ out) {
    const unsigned wid  = threadIdx.x >> 5;
    const unsigned lane = threadIdx.x & 31u;
    const bool     l31  = (lane == 31u);

    const unsigned zseg = blockIdx.x % NZSEG;
    const unsigned rest = blockIdx.x / NZSEG;
    const unsigned xc   = rest % XC;
    const unsigned g    = rest / XC;

    const unsigned zb = zseg * 128u;
    const unsigned y  = g * OWN + wid;
    const bool rowload = (y <= 384u);
    const bool rowown  = (wid < OWN);
    const bool ypair   = rowown && (y < 384u);
    const bool hseg31  = (zseg == NZSEG - 1u) && l31;  // z=384 column diffs

    const unsigned as = (384u * xc) / XC;
    const unsigned ae = (384u * (xc + 1u)) / XC;
    const bool lastc  = (ae == 384u);
    const int  mid    = (int)(ae - as);

    __shared__ float sm[4][WPB][132];   // 4-buffer rotation

    const float* p = occ + (size_t)y * ROW + zb + lane + (size_t)as * PLANE;

    float s0 = 0.f, s1 = 0.f;
    float v0=0.f,v1=0.f,v2=0.f,v3=0.f,hc=0.f;   // plane to publish/compute
    float n0=0.f,n1=0.f,n2=0.f,n3=0.f,hn=0.f;   // prefetched next plane

    #define LDN() do { p += PLANE;                              \
        n0=__ldg(p); n1=__ldg(p+32);                            \
        n2=__ldg(p+64); n3=__ldg(p+96);                         \
        if (l31) hn=__ldg(p+97); } while(0)

    #define PUB(B) do { float* r_ = sm[B][wid];                 \
        r_[lane]=v0; r_[lane+32u]=v1;                           \
        r_[lane+64u]=v2; r_[lane+96u]=v3;                       \
        if (l31) r_[128]=hc; } while(0)

    #define ZY(B) do {                                                      \
        const float* r_ = sm[B][wid];                                       \
        s0 += fabsf(r_[lane+1u]  - v0) + fabsf(r_[lane+33u] - v1);          \
        s1 += fabsf(r_[lane+65u] - v2) + fabsf(r_[lane+97u] - v3);          \
        if (ypair) {                                                        \
            const float* q_ = sm[B][wid+1u];                                \
            s0 += fabsf(q_[lane]      - v0) + fabsf(q_[lane+32u] - v1);     \
            s1 += fabsf(q_[lane+64u]  - v2) + fabsf(q_[lane+96u] - v3);     \
            if (hseg31) s0 += fabsf(q_[128] - hc);                          \
        } } while(0)

    // x-diff pair (x-1, x): v vs previous plane's smem buffer
    #define XD(B) do {                                                      \
        const float* r_ = sm[B][wid];                                       \
        s0 += fabsf(v0 - r_[lane])       + fabsf(v1 - r_[lane+32u]);        \
        s1 += fabsf(v2 - r_[lane+64u])   + fabsf(v3 - r_[lane+96u]);        \
        if (hseg31) s0 += fabsf(hc - r_[128]); } while(0)

    #define ROT() do { v0=n0; v1=n1; v2=n2; v3=n3; hc=hn; } while(0)

    // ---- preload plane as ----
    if (rowload) {
        v0=__ldg(p); v1=__ldg(p+32); v2=__ldg(p+64); v3=__ldg(p+96);
        if (l31) hc=__ldg(p+97);
    }

    // ---- j = 0 (plane as): z/y only ----
    if (rowload) { PUB(0u); LDN(); }
    __syncthreads();
    if (rowown) ZY(0u);
    ROT();

    // ---- steady j = 1..mid-1: branch-free body ----
    #pragma unroll 2
    for (int j = 1; j < mid; ++j) {
        const unsigned b = (unsigned)j & 3u;
        if (rowload) { PUB(b); LDN(); }
        __syncthreads();
        if (rowown) { XD((b + 3u) & 3u); ZY(b); }
        ROT();
    }

    // ---- final j = mid (plane ae): x-diff always, z/y only if lastc ----
    {
        const unsigned b = (unsigned)mid & 3u;
        if (rowload) PUB(b);
        __syncthreads();
        if (rowown) { XD((b + 3u) & 3u); if (lastc) ZY(b); }
    }

    // ---- block reduction ----
    float s = s0 + s1;
    #pragma unroll
    for (int o = 16; o > 0; o >>= 1)
        s += __shfl_down_sync(0xffffffffu, s, o);

    __shared__ float    ws[WPB];
    __shared__ unsigned islast_s;
    if (lane == 0u) ws[wid] = s;
    __syncthreads();
    if (threadIdx.x == 0u) {
        float t = 0.f;
        #pragma unroll
        for (unsigned i = 0; i < WPB; ++i) t += ws[i];
        g_part[blockIdx.x] = (double)t;
        __threadfence();
        unsigned old = atomicAdd(&g_count, 1u);
        islast_s = (old == NBLOCKS - 1u) ? 1u : 0u;
    }
    __syncthreads();

    // ---- last block folds partials (single launch total) ----
    if (islast_s) {
        double d = 0.0;
        for (unsigned i = threadIdx.x; i < NBLOCKS; i += 256u)
            d += g_part[i];
        __shared__ double dsm[256];
        dsm[threadIdx.x] = d;
        __syncthreads();
        #pragma unroll
        for (int st = 128; st > 0; st >>= 1) {
            if ((int)threadIdx.x < st) dsm[threadIdx.x] += dsm[threadIdx.x + st];
            __syncthreads();
        }
        if (threadIdx.x == 0u) {
            out[0] = (float)dsm[0];
            g_count = 0u;   // reset for next graph replay
        }
    }
}

extern "C" void kernel_launch(void* const* d_in, const int* in_sizes, int n_in,
                              void* d_out, int out_size) {
    const float* occ = (const float*)d_in[0];
    float* out = (float*)d_out;
    occ_main<<<NBLOCKS, 256>>>(occ, out);
}

// round 11
// speedup vs baseline: 1.4944x; 1.4944x over previous
#include <cuda_runtime.h>

// Occupancy connectivity loss over a 385^3 fp32 grid, C order:
//   f = x*385^2 + y*385 + z
// Warp-autonomous design: NO block barriers, NO shared-memory data exchange.
// Each warp owns a 7(y) x 31(z) tile and marches 48 planes in x:
//   rows 0..6 owned, row 7 = y-halo (in registers)
//   lanes: z = zb + lane, zb = 31*ztile (tiles overlap by 1 column)
//   y-diff: in-register between adjacent row registers
//   z-diff: shfl_down(row, 1), lanes 0..30 accumulate
//   x-diff: vs prefetched next plane's registers
// Boundary handling by clamped duplicate loads (diff contributes exact 0).

#define ROW    385u
#define PLANE  148225u
#define NZT    13u                 // z tiles: zb = 0,31,...,372
#define NYG    55u                 // y groups of 7 owned rows
#define XC     8u                  // x chunks of 48 planes
#define WPB    8u
#define NTASKS (NZT * NYG * XC)    // 5720 warp tasks
#define NBLOCKS (NTASKS / WPB)     // 715

__device__ double   g_part[NBLOCKS];
__device__ unsigned g_count = 0;

__global__ void __launch_bounds__(256, 5)
occ_main(const float* __restrict__ occ, float* __restrict__ out) {
    const unsigned wid  = threadIdx.x >> 5;
    const unsigned lane = threadIdx.x & 31u;

    const unsigned w  = blockIdx.x * WPB + wid;
    const unsigned zt = w % NZT;
    const unsigned r1 = w / NZT;
    const unsigned yg = r1 % NYG;
    const unsigned xc = r1 / NYG;

    const unsigned zb = zt * 31u;
    const unsigned z  = min(zb + lane, 384u);       // clamp: dup loads are harmless
    const unsigned yb = yg * 7u;

    const bool lastzt = (zt == NZT - 1u);
    const bool yxm = lane < (lastzt ? 13u : 31u);   // owned z columns
    const bool zm  = lane < (lastzt ? 12u : 31u);   // owned z pairs

    const unsigned as    = 48u * xc;                // planes [as, as+48]
    const bool     lastc = (xc == XC - 1u);
    // last y group: row 7 duplicates row 6 (y=384) -> y-diff contributes 0
    const unsigned off7  = (yg == NYG - 1u) ? 6u * ROW : 7u * ROW;

    const float* p = occ + (size_t)yb * ROW + z + (size_t)as * PLANE;

    float s0 = 0.f, s1 = 0.f;
    float v[8], n[8];

    v[0]=__ldg(p);          v[1]=__ldg(p+ROW);      v[2]=__ldg(p+2u*ROW);
    v[3]=__ldg(p+3u*ROW);   v[4]=__ldg(p+4u*ROW);   v[5]=__ldg(p+5u*ROW);
    v[6]=__ldg(p+6u*ROW);   v[7]=__ldg(p+off7);

    #define LOAD(A) do { p += PLANE;                                        \
        A[0]=__ldg(p);        A[1]=__ldg(p+ROW);    A[2]=__ldg(p+2u*ROW);   \
        A[3]=__ldg(p+3u*ROW); A[4]=__ldg(p+4u*ROW); A[5]=__ldg(p+5u*ROW);   \
        A[6]=__ldg(p+6u*ROW); A[7]=__ldg(p+off7); } while(0)

    // diffs for the plane held in V; N = next plane (x-diff partner)
    #define BODY(V,N) do {                                                  \
        _Pragma("unroll")                                                   \
        for (int r = 0; r < 7; ++r) {                                       \
            float zn = __shfl_down_sync(0xffffffffu, V[r], 1);              \
            float dz = fabsf(zn - V[r]);                                    \
            float dy = fabsf(V[r+1] - V[r]);                                \
            float dx = fabsf(N[r]   - V[r]);                                \
            if (zm)  s0 += dz;                                              \
            if (yxm) { s0 += dy; s1 += dx; }                                \
        } } while(0)

    // 48 x-pairs per chunk; unrolled x2 with register-role swap (no moves)
    #pragma unroll 1
    for (int i = 0; i < 48; i += 2) {
        LOAD(n);
        BODY(v, n);
        LOAD(v);
        BODY(n, v);
    }

    // final plane x = 384 (last chunk only): z/y diffs, no x-diff
    if (lastc) {
        #pragma unroll
        for (int r = 0; r < 7; ++r) {
            float zn = __shfl_down_sync(0xffffffffu, v[r], 1);
            float dz = fabsf(zn - v[r]);
            float dy = fabsf(v[r+1] - v[r]);
            if (zm)  s0 += dz;
            if (yxm) s0 += dy;
        }
    }

    // ---- block reduction ----
    float s = s0 + s1;
    #pragma unroll
    for (int o = 16; o > 0; o >>= 1)
        s += __shfl_down_sync(0xffffffffu, s, o);

    __shared__ float    ws[WPB];
    __shared__ unsigned islast_s;
    if (lane == 0u) ws[wid] = s;
    __syncthreads();
    if (threadIdx.x == 0u) {
        float t = 0.f;
        #pragma unroll
        for (unsigned i = 0; i < WPB; ++i) t += ws[i];
        g_part[blockIdx.x] = (double)t;
        __threadfence();
        unsigned old = atomicAdd(&g_count, 1u);
        islast_s = (old == NBLOCKS - 1u) ? 1u : 0u;
    }
    __syncthreads();

    // ---- last block folds partials (single launch total) ----
    if (islast_s) {
        double d = 0.0;
        for (unsigned i = threadIdx.x; i < NBLOCKS; i += 256u)
            d += g_part[i];
        __shared__ double dsm[256];
        dsm[threadIdx.x] = d;
        __syncthreads();
        #pragma unroll
        for (int st = 128; st > 0; st >>= 1) {
            if ((int)threadIdx.x < st) dsm[threadIdx.x] += dsm[threadIdx.x + st];
            __syncthreads();
        }
        if (threadIdx.x == 0u) {
            out[0] = (float)dsm[0];
            g_count = 0u;   // reset for next graph replay
        }
    }
}

extern "C" void kernel_launch(void* const* d_in, const int* in_sizes, int n_in,
                              void* d_out, int out_size) {
    const float* occ = (const float*)d_in[0];
    float* out = (float*)d_out;
    occ_main<<<NBLOCKS, 256>>>(occ, out);
}